// round 13
// baseline (speedup 1.0000x reference)
#include <cuda_runtime.h>
#include <float.h>
#include <math.h>

// Problem geometry
#define HH 512
#define WW 512
#define SLICES 128                 // B*P = 64*2
#define NB 32                      // blocks per slice
#define TPB 256                    // threads per block
#define NBLOCKS (SLICES*NB)        // 4096
#define ELEMS_PER_SLICE (HH*WW)    // 262144
#define ELEMS_PER_BLOCK (ELEMS_PER_SLICE/NB)   // 8192
#define VEC4_PER_BLOCK  (ELEMS_PER_BLOCK/4)    // 2048
#define VEC4_PER_THREAD (VEC4_PER_BLOCK/TPB)   // 8

// Per-block partials (static device scratch; 16B-aligned for float4 loads)
__device__ __align__(16) float g_s [NBLOCKS];
__device__ __align__(16) float g_sx[NBLOCKS];
__device__ __align__(16) float g_sy[NBLOCKS];
__device__ __align__(16) float g_tv[NBLOCKS];
__device__ __align__(16) int   g_ti[NBLOCKS];

__global__ __launch_bounds__(TPB, 6)
void dsnt_pass1(const float4* __restrict__ inp, const float4* __restrict__ tgt)
{
    const int blk   = blockIdx.x;          // 0..NBLOCKS-1
    const int slice = blk >> 5;            // /NB
    const int sub   = blk & (NB-1);
    const int tid   = threadIdx.x;

    const int slice_base4 = slice * (ELEMS_PER_SLICE/4);
    const int chunk_base4 = sub * VEC4_PER_BLOCK;

    // Block stride = TPB*4 = 1024 elements = exactly 2 rows:
    //   col (ei & 511) is CONSTANT per thread across all iterations;
    //   row advances by exactly 2 per iteration.
    const int ei0  = (chunk_base4 + tid) << 2;
    const float colf1 = (float)((ei0 & 511) + 1);   // col+1, constant
    float rowf = (float)((ei0 >> 9) + 1);           // row+1, += 2 per iter

    float s = 0.f, w = 0.f, sy = 0.f;   // sx reconstructed at the end
    float tv = -FLT_MAX;
    int   ti = 0x7fffffff;

#pragma unroll
    for (int k = 0; k < VEC4_PER_THREAD; k++) {
        const int local4 = k * TPB + tid;               // block-stride, coalesced
        const int g4     = slice_base4 + chunk_base4 + local4;
        const float4 v = inp[g4];
        const float4 t = tgt[g4];

        const float e0 = __expf(v.x);
        const float e1 = __expf(v.y);
        const float e2 = __expf(v.z);
        const float e3 = __expf(v.w);
        const float es = (e0 + e1) + (e2 + e3);
        s  += es;
        // intra-quad x-weight: e1*1 + e2*2 + e3*3
        w  += fmaf(e2, 2.0f, e1) + e3 * 3.0f;
        sy  = fmaf(es, rowf, sy);
        rowf += 2.0f;

        // target running argmax (indices visited in increasing order)
        const int ei = (chunk_base4 + local4) << 2;
        if (t.x > tv) { tv = t.x; ti = ei;     }
        if (t.y > tv) { tv = t.y; ti = ei + 1; }
        if (t.z > tv) { tv = t.z; ti = ei + 2; }
        if (t.w > tv) { tv = t.w; ti = ei + 3; }
    }

    // sx = (col+1)*sum(es) + sum(e1 + 2e2 + 3e3)
    float sx = fmaf(colf1, s, w);

    // ---- warp reduce ----
#pragma unroll
    for (int off = 16; off > 0; off >>= 1) {
        s  += __shfl_down_sync(0xffffffffu, s,  off);
        sx += __shfl_down_sync(0xffffffffu, sx, off);
        sy += __shfl_down_sync(0xffffffffu, sy, off);
        float ov = __shfl_down_sync(0xffffffffu, tv, off);
        int   oi = __shfl_down_sync(0xffffffffu, ti, off);
        if (ov > tv || (ov == tv && oi < ti)) { tv = ov; ti = oi; }
    }

    __shared__ float sh_s[8], sh_sx[8], sh_sy[8], sh_tv[8];
    __shared__ int   sh_ti[8];
    const int wid = tid >> 5;
    const int lid = tid & 31;
    if (lid == 0) { sh_s[wid]=s; sh_sx[wid]=sx; sh_sy[wid]=sy; sh_tv[wid]=tv; sh_ti[wid]=ti; }
    __syncthreads();

    if (wid == 0) {
        s  = (lid < 8) ? sh_s [lid] : 0.f;
        sx = (lid < 8) ? sh_sx[lid] : 0.f;
        sy = (lid < 8) ? sh_sy[lid] : 0.f;
        tv = (lid < 8) ? sh_tv[lid] : -FLT_MAX;
        ti = (lid < 8) ? sh_ti[lid] : 0x7fffffff;
#pragma unroll
        for (int off = 4; off > 0; off >>= 1) {
            s  += __shfl_down_sync(0xffffffffu, s,  off);
            sx += __shfl_down_sync(0xffffffffu, sx, off);
            sy += __shfl_down_sync(0xffffffffu, sy, off);
            float ov = __shfl_down_sync(0xffffffffu, tv, off);
            int   oi = __shfl_down_sync(0xffffffffu, ti, off);
            if (ov > tv || (ov == tv && oi < ti)) { tv = ov; ti = oi; }
        }
        if (lid == 0) {
            g_s [blk] = s;
            g_sx[blk] = sx;
            g_sy[blk] = sy;
            g_tv[blk] = tv;
            g_ti[blk] = ti;
        }
    }
}

// ---------------------------------------------------------------------------
// Pass 2 (proven R11 structure): 512 threads, 4 threads per slice, 8 partials
// per thread via float4/int4 loads -> MLP=10, one DRAM round-trip.
// ---------------------------------------------------------------------------
#define TPB2 512

__global__ __launch_bounds__(TPB2)
void dsnt_pass2(float* __restrict__ out)
{
    const int t = threadIdx.x;          // 0..511
    const int sl   = t >> 2;            // slice 0..127
    const int part = t & 3;             // 0..3 (8 partials each)

    __shared__ float sS [TPB2], sSX[TPB2], sSY[TPB2], sMV[TPB2];
    __shared__ int   sMI[TPB2];
    __shared__ float sh_px[SLICES], sh_py[SLICES], sh_tx[SLICES], sh_ty[SLICES];
    __shared__ float sh_red[64];

    // ---- phase 1: each thread reduces its 8 partials (vector loads) ----
    {
        const int v4 = sl * (NB/4) + part * 2;          // float4 index
        const float4 s0  = ((const float4*)g_s )[v4];
        const float4 s1  = ((const float4*)g_s )[v4+1];
        const float4 x0  = ((const float4*)g_sx)[v4];
        const float4 x1  = ((const float4*)g_sx)[v4+1];
        const float4 y0  = ((const float4*)g_sy)[v4];
        const float4 y1  = ((const float4*)g_sy)[v4+1];
        const float4 m0  = ((const float4*)g_tv)[v4];
        const float4 m1  = ((const float4*)g_tv)[v4+1];
        const int4   i0  = ((const int4*  )g_ti)[v4];
        const int4   i1  = ((const int4*  )g_ti)[v4+1];

        sS [t] = ((s0.x + s0.y) + (s0.z + s0.w)) + ((s1.x + s1.y) + (s1.z + s1.w));
        sSX[t] = ((x0.x + x0.y) + (x0.z + x0.w)) + ((x1.x + x1.y) + (x1.z + x1.w));
        sSY[t] = ((y0.x + y0.y) + (y0.z + y0.w)) + ((y1.x + y1.y) + (y1.z + y1.w));

        // argmax over 8 pairs; increasing index order, strict '>' keeps first max
        float mv = m0.x; int mi = i0.x;
        if (m0.y > mv) { mv = m0.y; mi = i0.y; }
        if (m0.z > mv) { mv = m0.z; mi = i0.z; }
        if (m0.w > mv) { mv = m0.w; mi = i0.w; }
        if (m1.x > mv) { mv = m1.x; mi = i1.x; }
        if (m1.y > mv) { mv = m1.y; mi = i1.y; }
        if (m1.z > mv) { mv = m1.z; mi = i1.z; }
        if (m1.w > mv) { mv = m1.w; mi = i1.w; }
        sMV[t] = mv;
        sMI[t] = mi;
    }
    __syncthreads();

    // ---- phase 2: combine the 4 sub-results per slice ----
    if (t < SLICES) {
        const int b = t * 4;
        float S  = ((sS [b] + sS [b+1]) + (sS [b+2] + sS [b+3]));
        float SX = ((sSX[b] + sSX[b+1]) + (sSX[b+2] + sSX[b+3]));
        float SY = ((sSY[b] + sSY[b+1]) + (sSY[b+2] + sSY[b+3]));
        float mv = sMV[b]; int mi = sMI[b];
        if (sMV[b+1] > mv) { mv = sMV[b+1]; mi = sMI[b+1]; }
        if (sMV[b+2] > mv) { mv = sMV[b+2]; mi = sMI[b+2]; }
        if (sMV[b+3] > mv) { mv = sMV[b+3]; mi = sMI[b+3]; }

        const float inv = 1.0f / (S * 512.0f);
        sh_px[t] = SX * inv;
        sh_py[t] = SY * inv;
        sh_tx[t] = (float)((mi & 511) + 1) * (1.0f / 512.0f);
        sh_ty[t] = (float)((mi >> 9)  + 1) * (1.0f / 512.0f);
    }
    __syncthreads();

    // ---- phase 3: per-batch loss terms ----
    if (t < 64) {
        const int p0 = 2 * t, p1 = 2 * t + 1;
        const float px0 = sh_px[p0], py0 = sh_py[p0];
        const float px1 = sh_px[p1], py1 = sh_py[p1];
        const float tx0 = sh_tx[p0], ty0 = sh_ty[p0];
        const float tx1 = sh_tx[p1], ty1 = sh_ty[p1];

        const float dx0 = tx0 - px0, dy0 = ty0 - py0;
        const float dx1 = tx1 - px1, dy1 = ty1 - py1;
        const float ed  = sqrtf(dx0*dx0 + dy0*dy0) + sqrtf(dx1*dx1 + dy1*dy1);

        const float pvx = px0 - px1, pvy = py0 - py1;
        const float tvx = tx0 - tx1, tvy = ty0 - ty1;
        const float pd  = sqrtf(pvx*pvx + pvy*pvy);
        const float td  = sqrtf(tvx*tvx + tvy*tvy);
        const float dot = pvx*tvx + pvy*tvy;

        sh_red[t] = ed + fabsf(pd - td) + (1.0f - cosf(dot / (pd * td)));
    }
    __syncthreads();

    // ---- phase 4: tree sum of 64 per-batch terms ----
    if (t < 32) {
        float a = sh_red[t] + sh_red[t + 32];
#pragma unroll
        for (int off = 16; off > 0; off >>= 1)
            a += __shfl_down_sync(0xffffffffu, a, off);
        if (t == 0) out[0] = a * (1.0f / 64.0f);
    }
}

extern "C" void kernel_launch(void* const* d_in, const int* in_sizes, int n_in,
                              void* d_out, int out_size)
{
    const float4* inp = (const float4*)d_in[0];
    const float4* tgt = (const float4*)d_in[1];
    float* out = (float*)d_out;

    dsnt_pass1<<<NBLOCKS, TPB>>>(inp, tgt);
    dsnt_pass2<<<1, TPB2>>>(out);
}

// round 14
// speedup vs baseline: 1.1290x; 1.1290x over previous
#include <cuda_runtime.h>
#include <float.h>
#include <math.h>

// Problem geometry
#define HH 512
#define WW 512
#define SLICES 128                 // B*P = 64*2
#define NB 16                      // blocks per slice (halved: fewer epilogues)
#define TPB 256                    // threads per block
#define NBLOCKS (SLICES*NB)        // 2048
#define ELEMS_PER_SLICE (HH*WW)    // 262144
#define ELEMS_PER_BLOCK (ELEMS_PER_SLICE/NB)   // 16384
#define VEC4_PER_BLOCK  (ELEMS_PER_BLOCK/4)    // 4096
#define VEC4_PER_THREAD (VEC4_PER_BLOCK/TPB)   // 16

// Per-block partials (static device scratch; 16B-aligned for float4 loads)
__device__ __align__(16) float g_s [NBLOCKS];
__device__ __align__(16) float g_sx[NBLOCKS];
__device__ __align__(16) float g_sy[NBLOCKS];
__device__ __align__(16) float g_tv[NBLOCKS];
__device__ __align__(16) int   g_ti[NBLOCKS];

__global__ __launch_bounds__(TPB)
void dsnt_pass1(const float4* __restrict__ inp, const float4* __restrict__ tgt)
{
    const int blk   = blockIdx.x;          // 0..NBLOCKS-1
    const int slice = blk / NB;
    const int sub   = blk % NB;
    const int tid   = threadIdx.x;

    const int slice_base4 = slice * (ELEMS_PER_SLICE/4);
    const int chunk_base4 = sub * VEC4_PER_BLOCK;

    float s = 0.f, sx = 0.f, sy = 0.f;
    float tv = -FLT_MAX;
    int   ti = 0x7fffffff;

#pragma unroll
    for (int k = 0; k < VEC4_PER_THREAD; k++) {
        const int local4 = k * TPB + tid;               // block-stride, coalesced
        const int g4     = slice_base4 + chunk_base4 + local4;
        const float4 v = inp[g4];
        const float4 t = tgt[g4];

        const int ei  = (chunk_base4 + local4) << 2;    // element index in slice
        const int row = ei >> 9;                        // /512
        const int col = ei & 511;

        const float e0 = __expf(v.x);
        const float e1 = __expf(v.y);
        const float e2 = __expf(v.z);
        const float e3 = __expf(v.w);
        const float es = (e0 + e1) + (e2 + e3);
        s  += es;
        sx += e0*(float)(col+1) + e1*(float)(col+2)
            + e2*(float)(col+3) + e3*(float)(col+4);
        sy += es * (float)(row+1);

        // target running argmax (indices visited in increasing order per thread)
        if (t.x > tv) { tv = t.x; ti = ei;     }
        if (t.y > tv) { tv = t.y; ti = ei + 1; }
        if (t.z > tv) { tv = t.z; ti = ei + 2; }
        if (t.w > tv) { tv = t.w; ti = ei + 3; }
    }

    // ---- warp reduce ----
#pragma unroll
    for (int off = 16; off > 0; off >>= 1) {
        s  += __shfl_down_sync(0xffffffffu, s,  off);
        sx += __shfl_down_sync(0xffffffffu, sx, off);
        sy += __shfl_down_sync(0xffffffffu, sy, off);
        float ov = __shfl_down_sync(0xffffffffu, tv, off);
        int   oi = __shfl_down_sync(0xffffffffu, ti, off);
        if (ov > tv || (ov == tv && oi < ti)) { tv = ov; ti = oi; }
    }

    __shared__ float sh_s[8], sh_sx[8], sh_sy[8], sh_tv[8];
    __shared__ int   sh_ti[8];
    const int wid = tid >> 5;
    const int lid = tid & 31;
    if (lid == 0) { sh_s[wid]=s; sh_sx[wid]=sx; sh_sy[wid]=sy; sh_tv[wid]=tv; sh_ti[wid]=ti; }
    __syncthreads();

    if (wid == 0) {
        s  = (lid < 8) ? sh_s [lid] : 0.f;
        sx = (lid < 8) ? sh_sx[lid] : 0.f;
        sy = (lid < 8) ? sh_sy[lid] : 0.f;
        tv = (lid < 8) ? sh_tv[lid] : -FLT_MAX;
        ti = (lid < 8) ? sh_ti[lid] : 0x7fffffff;
#pragma unroll
        for (int off = 4; off > 0; off >>= 1) {
            s  += __shfl_down_sync(0xffffffffu, s,  off);
            sx += __shfl_down_sync(0xffffffffu, sx, off);
            sy += __shfl_down_sync(0xffffffffu, sy, off);
            float ov = __shfl_down_sync(0xffffffffu, tv, off);
            int   oi = __shfl_down_sync(0xffffffffu, ti, off);
            if (ov > tv || (ov == tv && oi < ti)) { tv = ov; ti = oi; }
        }
        if (lid == 0) {
            g_s [blk] = s;
            g_sx[blk] = sx;
            g_sy[blk] = sy;
            g_tv[blk] = tv;
            g_ti[blk] = ti;
        }
    }
}

// ---------------------------------------------------------------------------
// Pass 2: PDL secondary. 512 threads, 4 threads per slice, 4 partials per
// thread via one float4/int4 load per array (5 independent 16B loads/thread).
// Launch overlaps pass1 tail; cudaGridDependencySynchronize() gates the reads.
// ---------------------------------------------------------------------------
#define TPB2 512

__global__ __launch_bounds__(TPB2)
void dsnt_pass2(float* __restrict__ out)
{
    const int t = threadIdx.x;          // 0..511
    const int sl   = t >> 2;            // slice 0..127
    const int part = t & 3;             // 0..3 (4 partials each)

    __shared__ float sS [TPB2], sSX[TPB2], sSY[TPB2], sMV[TPB2];
    __shared__ int   sMI[TPB2];
    __shared__ float sh_px[SLICES], sh_py[SLICES], sh_tx[SLICES], sh_ty[SLICES];
    __shared__ float sh_red[64];

    // Wait for pass1's memory to be visible (PDL: we may have launched early).
    cudaGridDependencySynchronize();

    // ---- phase 1: each thread reduces its 4 partials (vector loads) ----
    {
        const int v4 = sl * (NB/4) + part;              // float4 index
        const float4 s0 = ((const float4*)g_s )[v4];
        const float4 x0 = ((const float4*)g_sx)[v4];
        const float4 y0 = ((const float4*)g_sy)[v4];
        const float4 m0 = ((const float4*)g_tv)[v4];
        const int4   i0 = ((const int4*  )g_ti)[v4];

        sS [t] = (s0.x + s0.y) + (s0.z + s0.w);
        sSX[t] = (x0.x + x0.y) + (x0.z + x0.w);
        sSY[t] = (y0.x + y0.y) + (y0.z + y0.w);

        // argmax over 4 pairs; increasing index order, strict '>' keeps first max
        float mv = m0.x; int mi = i0.x;
        if (m0.y > mv) { mv = m0.y; mi = i0.y; }
        if (m0.z > mv) { mv = m0.z; mi = i0.z; }
        if (m0.w > mv) { mv = m0.w; mi = i0.w; }
        sMV[t] = mv;
        sMI[t] = mi;
    }
    __syncthreads();

    // ---- phase 2: combine the 4 sub-results per slice ----
    if (t < SLICES) {
        const int b = t * 4;
        float S  = ((sS [b] + sS [b+1]) + (sS [b+2] + sS [b+3]));
        float SX = ((sSX[b] + sSX[b+1]) + (sSX[b+2] + sSX[b+3]));
        float SY = ((sSY[b] + sSY[b+1]) + (sSY[b+2] + sSY[b+3]));
        float mv = sMV[b]; int mi = sMI[b];
        if (sMV[b+1] > mv) { mv = sMV[b+1]; mi = sMI[b+1]; }
        if (sMV[b+2] > mv) { mv = sMV[b+2]; mi = sMI[b+2]; }
        if (sMV[b+3] > mv) { mv = sMV[b+3]; mi = sMI[b+3]; }

        const float inv = 1.0f / (S * 512.0f);
        sh_px[t] = SX * inv;
        sh_py[t] = SY * inv;
        sh_tx[t] = (float)((mi & 511) + 1) * (1.0f / 512.0f);
        sh_ty[t] = (float)((mi >> 9)  + 1) * (1.0f / 512.0f);
    }
    __syncthreads();

    // ---- phase 3: per-batch loss terms ----
    if (t < 64) {
        const int p0 = 2 * t, p1 = 2 * t + 1;
        const float px0 = sh_px[p0], py0 = sh_py[p0];
        const float px1 = sh_px[p1], py1 = sh_py[p1];
        const float tx0 = sh_tx[p0], ty0 = sh_ty[p0];
        const float tx1 = sh_tx[p1], ty1 = sh_ty[p1];

        const float dx0 = tx0 - px0, dy0 = ty0 - py0;
        const float dx1 = tx1 - px1, dy1 = ty1 - py1;
        const float ed  = sqrtf(dx0*dx0 + dy0*dy0) + sqrtf(dx1*dx1 + dy1*dy1);

        const float pvx = px0 - px1, pvy = py0 - py1;
        const float tvx = tx0 - tx1, tvy = ty0 - ty1;
        const float pd  = sqrtf(pvx*pvx + pvy*pvy);
        const float td  = sqrtf(tvx*tvx + tvy*tvy);
        const float dot = pvx*tvx + pvy*tvy;

        sh_red[t] = ed + fabsf(pd - td) + (1.0f - cosf(dot / (pd * td)));
    }
    __syncthreads();

    // ---- phase 4: tree sum of 64 per-batch terms ----
    if (t < 32) {
        float a = sh_red[t] + sh_red[t + 32];
#pragma unroll
        for (int off = 16; off > 0; off >>= 1)
            a += __shfl_down_sync(0xffffffffu, a, off);
        if (t == 0) out[0] = a * (1.0f / 64.0f);
    }
}

extern "C" void kernel_launch(void* const* d_in, const int* in_sizes, int n_in,
                              void* d_out, int out_size)
{
    const float4* inp = (const float4*)d_in[0];
    const float4* tgt = (const float4*)d_in[1];
    float* out = (float*)d_out;

    dsnt_pass1<<<NBLOCKS, TPB>>>(inp, tgt);

    // PDL launch for pass2: allowed to begin (preamble) while pass1 drains;
    // cudaGridDependencySynchronize() inside gates the data reads.
    cudaLaunchConfig_t cfg = {};
    cfg.gridDim  = dim3(1, 1, 1);
    cfg.blockDim = dim3(TPB2, 1, 1);
    cfg.dynamicSmemBytes = 0;
    cfg.stream = 0;
    cudaLaunchAttribute attrs[1];
    attrs[0].id = cudaLaunchAttributeProgrammaticStreamSerialization;
    attrs[0].val.programmaticStreamSerializationAllowed = 1;
    cfg.attrs = attrs;
    cfg.numAttrs = 1;
    cudaLaunchKernelEx(&cfg, dsnt_pass2, out);
}